// round 7
// baseline (speedup 1.0000x reference)
#include <cuda_runtime.h>
#include <cuda_bf16.h>
#include <stdint.h>

// Problem constants (fixed by the dataset)
#define F_DIM 16384     // n_features
#define D_DIM 768       // d_model
#define M_CONN 262144   // n_connections
#define BS_DIM 1024     // B*S = 2*512

// ---------------------------------------------------------------------------
// Static scratch (no cudaMalloc allowed)
// ---------------------------------------------------------------------------
__device__ float  g_udT[(size_t)F_DIM * D_DIM];    // up_decoder transposed [F, D]   48 MB
__device__ float  g_upT[(size_t)F_DIM * BS_DIM];   // up_facts  transposed [F, BS]   64 MB
__device__ float  g_outT[(size_t)F_DIM * BS_DIM];  // output    transposed [F, BS]   64 MB
__device__ float2 g_jv[M_CONN];                    // packed {j as float-bits, value} 2 MB
__device__ int    g_rowptr[F_DIM + 1];             // CSR row pointers (i sorted)
__device__ int    g_ii[M_CONN];                    // normalized int32 i indices  1 MB
__device__ int    g_jj[M_CONN];                    // normalized int32 j indices  1 MB
__device__ int    g_is64;                          // 1 if index buffers are int64

// ---------------------------------------------------------------------------
// Dtype probe: if the j_indices buffer is int64 (values < F fit in 32 bits),
// every odd 32-bit word is the zero high-half. If int32, odd words are random
// indices in [0, F): P(64 sampled words all zero) ~ (1/16384)^64 ~ 0.
// Max sampled word index 63*4094+1 = 257,923 < 262,144 words even for int32.
// ---------------------------------------------------------------------------
__global__ void detect_dtype_kernel(const unsigned int* __restrict__ jw)
{
    unsigned int acc = 0;
#pragma unroll
    for (int s = 0; s < 64; ++s) {
        size_t idx = (size_t)s * 4094 + 1;        // odd word indices, spread
        acc |= jw[idx];
    }
    g_is64 = (acc == 0) ? 1 : 0;
}

// ---------------------------------------------------------------------------
// Normalize both index arrays to int32 device globals.
// ---------------------------------------------------------------------------
__global__ void convert_idx_kernel(const void* __restrict__ ii,
                                   const void* __restrict__ jj)
{
    int m = blockIdx.x * 256 + threadIdx.x;
    if (m >= M_CONN) return;
    if (g_is64) {
        g_ii[m] = (int)((const long long*)ii)[m];
        g_jj[m] = (int)((const long long*)jj)[m];
    } else {
        g_ii[m] = ((const int*)ii)[m];
        g_jj[m] = ((const int*)jj)[m];
    }
}

// ---------------------------------------------------------------------------
// Tiled transpose: in[rows, cols] -> out[cols, rows]. Block (32, 8).
// ---------------------------------------------------------------------------
__global__ void transpose_kernel(const float* __restrict__ in,
                                 float* __restrict__ out,
                                 int rows, int cols)
{
    __shared__ float tile[32][33];
    int c = blockIdx.x * 32 + threadIdx.x;
    int r0 = blockIdx.y * 32;

#pragma unroll
    for (int k = 0; k < 32; k += 8) {
        int r = r0 + threadIdx.y + k;
        if (r < rows && c < cols)
            tile[threadIdx.y + k][threadIdx.x] = in[(size_t)r * cols + c];
    }
    __syncthreads();

    int oc = r0 + threadIdx.x;                  // output column = input row
#pragma unroll
    for (int k = 0; k < 32; k += 8) {
        int orow = blockIdx.x * 32 + threadIdx.y + k;   // output row = input col
        if (orow < cols && oc < rows)
            out[(size_t)orow * rows + oc] = tile[threadIdx.x][threadIdx.y + k];
    }
}

// ---------------------------------------------------------------------------
// CSR row pointers: g_ii is sorted -> binary search lower_bound per row.
// ---------------------------------------------------------------------------
__global__ void rowptr_kernel()
{
    int r = blockIdx.x * 256 + threadIdx.x;
    if (r > F_DIM) return;
    int lo = 0, hi = M_CONN;
    while (lo < hi) {
        int mid = (lo + hi) >> 1;
        if (g_ii[mid] < r) lo = mid + 1; else hi = mid;
    }
    g_rowptr[r] = lo;
}

// ---------------------------------------------------------------------------
// values: one warp per connection m.
//   g_jv[m] = { __int_as_float(j_m), dot(de[i_m,:], udT[j_m,:]) }
// Block (32, 8): 8 warps -> 8 connections per CTA. Sorted i => consecutive
// warps usually share the same de row (L1 hits).
// ---------------------------------------------------------------------------
__global__ void values_kernel(const float* __restrict__ de)
{
    int m = blockIdx.x * 8 + threadIdx.y;
    int lane = threadIdx.x;

    int i = g_ii[m];
    int j = g_jj[m];

    const float4* a = reinterpret_cast<const float4*>(de + (size_t)i * D_DIM);
    const float4* b = reinterpret_cast<const float4*>(g_udT + (size_t)j * D_DIM);

    float s = 0.f;
#pragma unroll
    for (int it = 0; it < 6; ++it) {                 // 6 * 32 * 4 = 768
        float4 av = __ldg(&a[lane + it * 32]);
        float4 bv = __ldg(&b[lane + it * 32]);
        s += av.x * bv.x + av.y * bv.y + av.z * bv.z + av.w * bv.w;
    }
#pragma unroll
    for (int off = 16; off; off >>= 1)
        s += __shfl_xor_sync(0xffffffffu, s, off);
    if (lane == 0)
        g_jv[m] = make_float2(__int_as_float(j), s);
}

// ---------------------------------------------------------------------------
// SpMM: out_T[i, :] = sum_{k in row(i)} value_k * up_T[j_k, :]
// One CTA per sparse row i. 256 threads x float4 = 1024 bs columns, register
// accumulation, one coalesced 4 KB row load of up_T per nnz, one 8B packed
// (j, value) scalar load per nnz.
// ---------------------------------------------------------------------------
__global__ void __launch_bounds__(256) spmm_kernel()
{
    int i = blockIdx.x;
    int t = threadIdx.x;
    int kbeg = g_rowptr[i];
    int kend = g_rowptr[i + 1];

    const float4* upT4 = reinterpret_cast<const float4*>(g_upT);
    float4 acc = make_float4(0.f, 0.f, 0.f, 0.f);

    int k = kbeg;
    if (k < kend) {
        float2 jv = __ldg(&g_jv[k]);
        for (; k + 1 < kend; ++k) {
            float2 jvn = __ldg(&g_jv[k + 1]);          // pipeline next pair
            int   j = __float_as_int(jv.x);
            float v = jv.y;
            float4 u = __ldg(&upT4[(size_t)j * (BS_DIM / 4) + t]);
            acc.x += v * u.x; acc.y += v * u.y;
            acc.z += v * u.z; acc.w += v * u.w;
            jv = jvn;
        }
        int   j = __float_as_int(jv.x);
        float v = jv.y;
        float4 u = __ldg(&upT4[(size_t)j * (BS_DIM / 4) + t]);
        acc.x += v * u.x; acc.y += v * u.y;
        acc.z += v * u.z; acc.w += v * u.w;
    }

    reinterpret_cast<float4*>(g_outT)[(size_t)i * (BS_DIM / 4) + t] = acc;
}

// ---------------------------------------------------------------------------
// kernel_launch — input order per metadata:
//   0: up_facts     f32 [B, S, F]     (2*512*16384)
//   1: down_encoder f32 [F, D]
//   2: up_decoder   f32 [D, F]
//   3: i_indices    int (32 or 64, detected at runtime) [M]
//   4: j_indices    int (32 or 64, detected at runtime) [M]
// output: f32 [B, S, F]
// ---------------------------------------------------------------------------
extern "C" void kernel_launch(void* const* d_in, const int* in_sizes, int n_in,
                              void* d_out, int out_size)
{
    const float* up  = (const float*)d_in[0];
    const float* de  = (const float*)d_in[1];
    const float* ud  = (const float*)d_in[2];
    const void*  ii  = d_in[3];
    const void*  jj  = d_in[4];
    float*       out = (float*)d_out;

    float* udT;  cudaGetSymbolAddress((void**)&udT,  g_udT);
    float* upT;  cudaGetSymbolAddress((void**)&upT,  g_upT);
    float* outT; cudaGetSymbolAddress((void**)&outT, g_outT);

    // 0. Detect index dtype and normalize to int32
    detect_dtype_kernel<<<1, 1>>>((const unsigned int*)jj);
    convert_idx_kernel<<<(M_CONN + 255) / 256, 256>>>(ii, jj);

    // 1. Transpose up_decoder [D, F] -> ud_T [F, D]
    {
        dim3 grid(F_DIM / 32, D_DIM / 32);
        transpose_kernel<<<grid, dim3(32, 8)>>>(ud, udT, D_DIM, F_DIM);
    }
    // 2. Transpose up_facts [BS, F] -> up_T [F, BS]
    {
        dim3 grid(F_DIM / 32, BS_DIM / 32);
        transpose_kernel<<<grid, dim3(32, 8)>>>(up, upT, BS_DIM, F_DIM);
    }
    // 3. CSR row pointers from sorted i indices
    rowptr_kernel<<<(F_DIM + 1 + 255) / 256, 256>>>();

    // 4. Per-connection virtual weight values (+ packed j)
    values_kernel<<<M_CONN / 8, dim3(32, 8)>>>(de);

    // 5. SpMM into transposed output
    spmm_kernel<<<F_DIM, 256>>>();

    // 6. Transpose out_T [F, BS] -> out [BS, F]
    {
        dim3 grid(BS_DIM / 32, F_DIM / 32);
        transpose_kernel<<<grid, dim3(32, 8)>>>(outT, out, F_DIM, BS_DIM);
    }
}

// round 15
// speedup vs baseline: 1.0338x; 1.0338x over previous
#include <cuda_runtime.h>
#include <cuda_bf16.h>
#include <stdint.h>

// Problem constants (fixed by the dataset)
#define F_DIM 16384     // n_features
#define D_DIM 768       // d_model
#define M_CONN 262144   // n_connections
#define BS_DIM 1024     // B*S = 2*512

// ---------------------------------------------------------------------------
// Static scratch (no cudaMalloc allowed)
// ---------------------------------------------------------------------------
__device__ float  g_udT[(size_t)F_DIM * D_DIM];    // up_decoder transposed [F, D]   48 MB
__device__ float  g_upT[(size_t)F_DIM * BS_DIM];   // up_facts  transposed [F, BS]   64 MB
__device__ float2 g_jv[M_CONN];                    // packed {j as float-bits, value} 2 MB
__device__ int    g_rowptr[F_DIM + 1];             // CSR row pointers (i sorted)
__device__ int    g_ii[M_CONN];                    // normalized int32 i indices  1 MB
__device__ int    g_jj[M_CONN];                    // normalized int32 j indices  1 MB
__device__ int    g_is64;                          // 1 if index buffers are int64

// ---------------------------------------------------------------------------
// Dtype probe: if the j_indices buffer is int64 (values < F fit in 32 bits),
// every odd 32-bit word is the zero high-half. If int32, odd words are random
// indices in [0, F): P(64 sampled words all zero) ~ (1/16384)^64 ~ 0.
// Max sampled word index 63*4094+1 = 257,923 < 262,144 words even for int32.
// ---------------------------------------------------------------------------
__global__ void detect_dtype_kernel(const unsigned int* __restrict__ jw)
{
    unsigned int acc = 0;
#pragma unroll
    for (int s = 0; s < 64; ++s) {
        size_t idx = (size_t)s * 4094 + 1;        // odd word indices, spread
        acc |= jw[idx];
    }
    g_is64 = (acc == 0) ? 1 : 0;
}

// ---------------------------------------------------------------------------
// Normalize both index arrays to int32 device globals.
// ---------------------------------------------------------------------------
__global__ void convert_idx_kernel(const void* __restrict__ ii,
                                   const void* __restrict__ jj)
{
    int m = blockIdx.x * 256 + threadIdx.x;
    if (m >= M_CONN) return;
    if (g_is64) {
        g_ii[m] = (int)((const long long*)ii)[m];
        g_jj[m] = (int)((const long long*)jj)[m];
    } else {
        g_ii[m] = ((const int*)ii)[m];
        g_jj[m] = ((const int*)jj)[m];
    }
}

// ---------------------------------------------------------------------------
// Tiled transpose: in[rows, cols] -> out[cols, rows]. Block (32, 8).
// ---------------------------------------------------------------------------
__global__ void transpose_kernel(const float* __restrict__ in,
                                 float* __restrict__ out,
                                 int rows, int cols)
{
    __shared__ float tile[32][33];
    int c = blockIdx.x * 32 + threadIdx.x;
    int r0 = blockIdx.y * 32;

#pragma unroll
    for (int k = 0; k < 32; k += 8) {
        int r = r0 + threadIdx.y + k;
        if (r < rows && c < cols)
            tile[threadIdx.y + k][threadIdx.x] = in[(size_t)r * cols + c];
    }
    __syncthreads();

    int oc = r0 + threadIdx.x;                  // output column = input row
#pragma unroll
    for (int k = 0; k < 32; k += 8) {
        int orow = blockIdx.x * 32 + threadIdx.y + k;   // output row = input col
        if (orow < cols && oc < rows)
            out[(size_t)orow * rows + oc] = tile[threadIdx.x][threadIdx.y + k];
    }
}

// ---------------------------------------------------------------------------
// CSR row pointers: g_ii is sorted -> binary search lower_bound per row.
// ---------------------------------------------------------------------------
__global__ void rowptr_kernel()
{
    int r = blockIdx.x * 256 + threadIdx.x;
    if (r > F_DIM) return;
    int lo = 0, hi = M_CONN;
    while (lo < hi) {
        int mid = (lo + hi) >> 1;
        if (g_ii[mid] < r) lo = mid + 1; else hi = mid;
    }
    g_rowptr[r] = lo;
}

// ---------------------------------------------------------------------------
// values: one warp per connection m.
//   g_jv[m] = { __int_as_float(j_m), dot(de[i_m,:], udT[j_m,:]) }
// Block (32, 8): 8 warps -> 8 connections per CTA. Sorted i => consecutive
// warps usually share the same de row (L1 hits).
// ---------------------------------------------------------------------------
__global__ void values_kernel(const float* __restrict__ de)
{
    int m = blockIdx.x * 8 + threadIdx.y;
    int lane = threadIdx.x;

    int i = g_ii[m];
    int j = g_jj[m];

    const float4* a = reinterpret_cast<const float4*>(de + (size_t)i * D_DIM);
    const float4* b = reinterpret_cast<const float4*>(g_udT + (size_t)j * D_DIM);

    float s = 0.f;
#pragma unroll
    for (int it = 0; it < 6; ++it) {                 // 6 * 32 * 4 = 768
        float4 av = __ldg(&a[lane + it * 32]);
        float4 bv = __ldg(&b[lane + it * 32]);
        s += av.x * bv.x + av.y * bv.y + av.z * bv.z + av.w * bv.w;
    }
#pragma unroll
    for (int off = 16; off; off >>= 1)
        s += __shfl_xor_sync(0xffffffffu, s, off);
    if (lane == 0)
        g_jv[m] = make_float2(__int_as_float(j), s);
}

// ---------------------------------------------------------------------------
// Fused SpMM + output transpose.
// CTA = (bs-chunk c of 128 cols, i-block ib of 32 rows). 256 threads:
//   cq = tid&31  -> float4 column within chunk (4 bs values)
//   rg = tid>>5  -> thread covers rows {rg, rg+8, rg+16, rg+24}
// Accumulate 4 rows x float4 in registers (coalesced 512B upT row-segment
// load per nnz), stage 32x128 tile in shared (stride 129 => conflict-free
// transposed gather), write out[bs, f] directly with coalesced streaming
// float4 stores (.cs — out is write-once, keep upT L2-resident).
// ---------------------------------------------------------------------------
__global__ void __launch_bounds__(256) spmm_fused_kernel(float* __restrict__ out)
{
    const int c   = blockIdx.x;         // bs chunk 0..7
    const int ib  = blockIdx.y;         // i block 0..511
    const int tid = threadIdx.x;
    const int cq  = tid & 31;
    const int rg  = tid >> 5;

    __shared__ float s[32 * 129];       // tile[r][bs_l], stride 129

    const float4* upT4 = reinterpret_cast<const float4*>(g_upT);

#pragma unroll
    for (int rr = 0; rr < 4; ++rr) {
        int r = rg + rr * 8;
        int i = ib * 32 + r;
        int kbeg = g_rowptr[i];         // warp-uniform
        int kend = g_rowptr[i + 1];

        float4 acc = make_float4(0.f, 0.f, 0.f, 0.f);
        int k = kbeg;
        if (k < kend) {
            float2 jv = __ldg(&g_jv[k]);
            for (; k + 1 < kend; ++k) {
                float2 jvn = __ldg(&g_jv[k + 1]);     // pipeline next pair
                int   j = __float_as_int(jv.x);
                float v = jv.y;
                float4 u = __ldg(&upT4[(size_t)j * 256 + c * 32 + cq]);
                acc.x += v * u.x; acc.y += v * u.y;
                acc.z += v * u.z; acc.w += v * u.w;
                jv = jvn;
            }
            int   j = __float_as_int(jv.x);
            float v = jv.y;
            float4 u = __ldg(&upT4[(size_t)j * 256 + c * 32 + cq]);
            acc.x += v * u.x; acc.y += v * u.y;
            acc.z += v * u.z; acc.w += v * u.w;
        }
        s[r * 129 + cq * 4 + 0] = acc.x;
        s[r * 129 + cq * 4 + 1] = acc.y;
        s[r * 129 + cq * 4 + 2] = acc.z;
        s[r * 129 + cq * 4 + 3] = acc.w;
    }
    __syncthreads();

    // Transposed write: out[bs, f], warp covers 4 bs rows x 32 f contiguous.
#pragma unroll
    for (int it = 0; it < 4; ++it) {
        int idx  = it * 256 + tid;       // 0..1023
        int bs_l = idx >> 3;             // 0..127
        int c4   = idx & 7;              // float4 index along f
        float4 val;
        val.x = s[(c4 * 4 + 0) * 129 + bs_l];
        val.y = s[(c4 * 4 + 1) * 129 + bs_l];
        val.z = s[(c4 * 4 + 2) * 129 + bs_l];
        val.w = s[(c4 * 4 + 3) * 129 + bs_l];
        int bs = c * 128 + bs_l;
        int f  = ib * 32 + c4 * 4;
        __stcs(reinterpret_cast<float4*>(out + (size_t)bs * F_DIM + f), val);
    }
}

// ---------------------------------------------------------------------------
// kernel_launch — input order per metadata:
//   0: up_facts     f32 [B, S, F]     (2*512*16384)
//   1: down_encoder f32 [F, D]
//   2: up_decoder   f32 [D, F]
//   3: i_indices    int (32 or 64, detected at runtime) [M]
//   4: j_indices    int (32 or 64, detected at runtime) [M]
// output: f32 [B, S, F]
// ---------------------------------------------------------------------------
extern "C" void kernel_launch(void* const* d_in, const int* in_sizes, int n_in,
                              void* d_out, int out_size)
{
    const float* up  = (const float*)d_in[0];
    const float* de  = (const float*)d_in[1];
    const float* ud  = (const float*)d_in[2];
    const void*  ii  = d_in[3];
    const void*  jj  = d_in[4];
    float*       out = (float*)d_out;

    float* udT;  cudaGetSymbolAddress((void**)&udT,  g_udT);
    float* upT;  cudaGetSymbolAddress((void**)&upT,  g_upT);

    // 0. Detect index dtype and normalize to int32
    detect_dtype_kernel<<<1, 1>>>((const unsigned int*)jj);
    convert_idx_kernel<<<(M_CONN + 255) / 256, 256>>>(ii, jj);

    // 1. Transpose up_decoder [D, F] -> ud_T [F, D]
    {
        dim3 grid(F_DIM / 32, D_DIM / 32);
        transpose_kernel<<<grid, dim3(32, 8)>>>(ud, udT, D_DIM, F_DIM);
    }
    // 2. Transpose up_facts [BS, F] -> up_T [F, BS]
    {
        dim3 grid(F_DIM / 32, BS_DIM / 32);
        transpose_kernel<<<grid, dim3(32, 8)>>>(up, upT, BS_DIM, F_DIM);
    }
    // 3. CSR row pointers from sorted i indices
    rowptr_kernel<<<(F_DIM + 1 + 255) / 256, 256>>>();

    // 4. Per-connection virtual weight values (+ packed j)
    values_kernel<<<M_CONN / 8, dim3(32, 8)>>>(de);

    // 5. Fused SpMM + output transpose (writes d_out directly)
    {
        dim3 grid(BS_DIM / 128, F_DIM / 32);   // (8, 512)
        spmm_fused_kernel<<<grid, 256>>>(out);
    }
}